// round 3
// baseline (speedup 1.0000x reference)
#include <cuda_runtime.h>
#include <cstdint>

// Fixed shapes from reference setup_inputs
#define BS   32
#define C    256
#define HW   4096          // 64*64
#define HID  32            // C / R
#define NPLANES (BS * C)   // 8192

// Scratch + sync state in device globals (zero-initialized at module load;
// self-reset at the end of each launch so graph replays are deterministic).
__device__ float        g_pooled[NPLANES];     // [BS, C] plane means
__device__ float4       g_coef[NPLANES];       // (a0, a1, q0, q1) per (b,c)
__device__ unsigned     g_cnt_pool[BS];        // pool-arrival counters
__device__ unsigned     g_cnt_done[BS];        // apply-completion counters
__device__ volatile int g_flag[BS];            // coef-ready flags

__global__ __launch_bounds__(256, 6) void fused_kernel(
    const float* __restrict__ x,
    const float* __restrict__ w1, const float* __restrict__ b1,
    const float* __restrict__ w2, const float* __restrict__ b2,
    float* __restrict__ out)
{
    const int p = blockIdx.x;          // plane = b*C + c
    const int b = p >> 8;
    const int c = p & 255;
    const int t = threadIdx.x;

    const float4* __restrict__ x4 = reinterpret_cast<const float4*>(x) + (size_t)p * (HW / 4);

    // ---- Phase 1: streaming load (evict-first; x is read exactly once) ----
    float4 v0 = __ldcs(&x4[t]);
    float4 v1 = __ldcs(&x4[t + 256]);
    float4 v2 = __ldcs(&x4[t + 512]);
    float4 v3 = __ldcs(&x4[t + 768]);

    float s = ((v0.x + v0.y) + (v0.z + v0.w))
            + ((v1.x + v1.y) + (v1.z + v1.w))
            + ((v2.x + v2.y) + (v2.z + v2.w))
            + ((v3.x + v3.y) + (v3.z + v3.w));

#pragma unroll
    for (int o = 16; o > 0; o >>= 1) s += __shfl_down_sync(0xffffffffu, s, o);

    __shared__ float ws[8];
    __shared__ int   s_last;
    if ((t & 31) == 0) ws[t >> 5] = s;
    __syncthreads();
    if (t < 8) {
        float v = ws[t];
#pragma unroll
        for (int o = 4; o > 0; o >>= 1) v += __shfl_down_sync(0xffu, v, o);
        if (t == 0) {
            g_pooled[p] = v * (1.0f / (float)HW);
            __threadfence();
            unsigned old = atomicAdd(&g_cnt_pool[b], 1u);
            s_last = (old == 255u);
        }
    }
    __syncthreads();

    // ---- Phase 2: last-arriving CTA of the batch computes coefficients ----
    if (s_last) {
        __threadfence();              // acquire: see peers' g_pooled writes
        __shared__ float sh[HID];
        if (t < HID) {
            float acc = b1[t];
            const float* __restrict__ w1r = w1 + t * C;
#pragma unroll 8
            for (int i = 0; i < C; ++i)
                acc = fmaf(__ldcg(&g_pooled[b * C + i]), w1r[i], acc);
            sh[t] = fmaxf(acc, 0.f);
        }
        __syncthreads();

        // thread t handles channel cc = t: 4 dot-products of length HID
        {
            const int cc = t;
            float z00 = b2[2 * cc];               // k=0, even (alpha)
            float z01 = b2[2 * cc + 1];           // k=0, odd  (beta)
            float z10 = b2[512 + 2 * cc];         // k=1, even
            float z11 = b2[512 + 2 * cc + 1];     // k=1, odd
            const float* __restrict__ r00 = w2 + (size_t)(2 * cc) * HID;
            const float* __restrict__ r01 = w2 + (size_t)(2 * cc + 1) * HID;
            const float* __restrict__ r10 = w2 + (size_t)(512 + 2 * cc) * HID;
            const float* __restrict__ r11 = w2 + (size_t)(512 + 2 * cc + 1) * HID;
#pragma unroll
            for (int h = 0; h < HID; ++h) {
                const float hv = sh[h];
                z00 = fmaf(hv, r00[h], z00);
                z01 = fmaf(hv, r01[h], z01);
                z10 = fmaf(hv, r10[h], z10);
                z11 = fmaf(hv, r11[h], z11);
            }
            float4 cf;
            cf.x = 1.0f + tanhf(0.5f * z00);          // a0 (init 1, lambda 1.0)
            cf.y =        tanhf(0.5f * z10);          // a1 (init 0)
            cf.z = 1.0f + 0.5f * tanhf(0.5f * z01);   // q0 (init 1, lambda 0.5)
            cf.w =        0.5f * tanhf(0.5f * z11);   // q1 (init 0)
            g_coef[b * C + cc] = cf;
        }
        __syncthreads();
        __threadfence();
        if (t == 0) g_flag[b] = 1;
    }

    // ---- Phase 3: wait for batch coefficients ----
    if (t == 0) {
        while (g_flag[b] == 0) __nanosleep(64);
    }
    __syncthreads();
    __threadfence();                  // acquire before reading g_coef

    const float4 cf = __ldcg(&g_coef[p]);
    const float a0 = cf.x, a1 = cf.y, q0 = cf.z, q1 = cf.w;

    // ---- Phase 4: apply from registers, streaming stores ----
    float4* __restrict__ o4 = reinterpret_cast<float4*>(out) + (size_t)p * (HW / 4);
    float4 r0, r1, r2, r3;
    r0.x = fmaxf(fmaf(v0.x, a0, q0), fmaf(v0.x, a1, q1));
    r0.y = fmaxf(fmaf(v0.y, a0, q0), fmaf(v0.y, a1, q1));
    r0.z = fmaxf(fmaf(v0.z, a0, q0), fmaf(v0.z, a1, q1));
    r0.w = fmaxf(fmaf(v0.w, a0, q0), fmaf(v0.w, a1, q1));
    r1.x = fmaxf(fmaf(v1.x, a0, q0), fmaf(v1.x, a1, q1));
    r1.y = fmaxf(fmaf(v1.y, a0, q0), fmaf(v1.y, a1, q1));
    r1.z = fmaxf(fmaf(v1.z, a0, q0), fmaf(v1.z, a1, q1));
    r1.w = fmaxf(fmaf(v1.w, a0, q0), fmaf(v1.w, a1, q1));
    r2.x = fmaxf(fmaf(v2.x, a0, q0), fmaf(v2.x, a1, q1));
    r2.y = fmaxf(fmaf(v2.y, a0, q0), fmaf(v2.y, a1, q1));
    r2.z = fmaxf(fmaf(v2.z, a0, q0), fmaf(v2.z, a1, q1));
    r2.w = fmaxf(fmaf(v2.w, a0, q0), fmaf(v2.w, a1, q1));
    r3.x = fmaxf(fmaf(v3.x, a0, q0), fmaf(v3.x, a1, q1));
    r3.y = fmaxf(fmaf(v3.y, a0, q0), fmaf(v3.y, a1, q1));
    r3.z = fmaxf(fmaf(v3.z, a0, q0), fmaf(v3.z, a1, q1));
    r3.w = fmaxf(fmaf(v3.w, a0, q0), fmaf(v3.w, a1, q1));

    __stcs(&o4[t],       r0);
    __stcs(&o4[t + 256], r1);
    __stcs(&o4[t + 512], r2);
    __stcs(&o4[t + 768], r3);

    // ---- Phase 5: self-reset sync state for graph replay ----
    if (t == 0) {
        unsigned old = atomicAdd(&g_cnt_done[b], 1u);
        if (old == 255u) {
            g_cnt_pool[b] = 0u;
            g_cnt_done[b] = 0u;
            g_flag[b]     = 0;
        }
    }
}

extern "C" void kernel_launch(void* const* d_in, const int* in_sizes, int n_in,
                              void* d_out, int out_size) {
    const float* x  = (const float*)d_in[0];
    const float* w1 = (const float*)d_in[1];
    const float* b1 = (const float*)d_in[2];
    const float* w2 = (const float*)d_in[3];
    const float* b2 = (const float*)d_in[4];
    float* out = (float*)d_out;

    fused_kernel<<<NPLANES, 256>>>(x, w1, b1, w2, b2, out);
}

// round 4
// speedup vs baseline: 3.9546x; 3.9546x over previous
#include <cuda_runtime.h>
#include <cstdint>

// Fixed shapes from reference setup_inputs
#define BS   32
#define C    256
#define HW   4096          // 64*64
#define HID  32            // C / R
#define NPLANES (BS * C)   // 8192

// Scratch in device globals. g_cnt is zero-initialized at module load and
// self-reset by the last CTA of each batch -> graph-replay deterministic.
__device__ float    g_pooled[NPLANES];   // [BS, C] plane means
__device__ float4   g_coef[NPLANES];     // (a0, a1, q0, q1) per (b,c)
__device__ unsigned g_cnt[BS];           // pool-arrival counters

// ---------------------------------------------------------------------------
// Kernel 1: mean pool over H*W (one CTA per plane) + inline coef compute by
// the LAST-arriving CTA of each batch (no waiting: everyone else just exits;
// the kernel boundary orders coef before apply).
// ---------------------------------------------------------------------------
__global__ __launch_bounds__(256) void pool_coef_kernel(
    const float* __restrict__ x,
    const float* __restrict__ w1, const float* __restrict__ b1,
    const float* __restrict__ w2, const float* __restrict__ b2)
{
    const int p = blockIdx.x;                  // plane = b*C + c
    const int b = p >> 8;
    const int t = threadIdx.x;

    const float4* __restrict__ x4 = reinterpret_cast<const float4*>(x) + (size_t)p * (HW / 4);

    // Front-batched loads (MLP=4); default .ca so x lingers in L2 for apply.
    float4 v0 = x4[t];
    float4 v1 = x4[t + 256];
    float4 v2 = x4[t + 512];
    float4 v3 = x4[t + 768];

    float s = ((v0.x + v0.y) + (v0.z + v0.w))
            + ((v1.x + v1.y) + (v1.z + v1.w))
            + ((v2.x + v2.y) + (v2.z + v2.w))
            + ((v3.x + v3.y) + (v3.z + v3.w));

#pragma unroll
    for (int o = 16; o > 0; o >>= 1) s += __shfl_down_sync(0xffffffffu, s, o);

    __shared__ float ws[8];
    __shared__ int   s_last;
    if ((t & 31) == 0) ws[t >> 5] = s;
    __syncthreads();
    if (t < 8) {
        float v = ws[t];
#pragma unroll
        for (int o = 4; o > 0; o >>= 1) v += __shfl_down_sync(0xffu, v, o);
        if (t == 0) {
            g_pooled[p] = v * (1.0f / (float)HW);
            __threadfence();                       // release g_pooled[p]
            unsigned old = atomicAdd(&g_cnt[b], 1u);
            s_last = (old == 255u);
        }
    }
    __syncthreads();

    if (!s_last) return;

    // ---- Last CTA of batch b: compute coefficients for all 256 channels ----
    __threadfence();                               // acquire peers' g_pooled
    __shared__ float sp[C];
    __shared__ float sh[HID];
    sp[t] = __ldcg(&g_pooled[b * C + t]);
    __syncthreads();

    if (t < HID) {
        float acc = b1[t];
        const float* __restrict__ w1r = w1 + t * C;
#pragma unroll 8
        for (int i = 0; i < C; ++i) acc = fmaf(sp[i], w1r[i], acc);
        sh[t] = fmaxf(acc, 0.f);
    }
    __syncthreads();

    {   // thread t -> channel t: 4 dot products of length HID
        const int cc = t;
        float z00 = b2[2 * cc];               // k=0 alpha
        float z01 = b2[2 * cc + 1];           // k=0 beta
        float z10 = b2[512 + 2 * cc];         // k=1 alpha
        float z11 = b2[512 + 2 * cc + 1];     // k=1 beta
        const float* __restrict__ r00 = w2 + (size_t)(2 * cc) * HID;
        const float* __restrict__ r01 = w2 + (size_t)(2 * cc + 1) * HID;
        const float* __restrict__ r10 = w2 + (size_t)(512 + 2 * cc) * HID;
        const float* __restrict__ r11 = w2 + (size_t)(512 + 2 * cc + 1) * HID;
#pragma unroll
        for (int h = 0; h < HID; ++h) {
            const float hv = sh[h];
            z00 = fmaf(hv, r00[h], z00);
            z01 = fmaf(hv, r01[h], z01);
            z10 = fmaf(hv, r10[h], z10);
            z11 = fmaf(hv, r11[h], z11);
        }
        float4 cf;
        cf.x = 1.0f + tanhf(0.5f * z00);          // a0 = 1 + 1.0*delta
        cf.y =        tanhf(0.5f * z10);          // a1 = 0 + 1.0*delta
        cf.z = 1.0f + 0.5f * tanhf(0.5f * z01);   // q0 = 1 + 0.5*delta
        cf.w =        0.5f * tanhf(0.5f * z11);   // q1 = 0 + 0.5*delta
        g_coef[b * C + cc] = cf;
    }

    if (t == 0) g_cnt[b] = 0u;   // reset for next graph replay
}

// ---------------------------------------------------------------------------
// Kernel 2: out = max(x*a0+q0, x*a1+q1). Two planes per CTA, 8 front-batched
// float4 loads per thread (MLP_p1=8). Reverse traversal consumes the tail of
// x left in L2 by the pool pass; __ldcs evicts x after use; __stcs keeps the
// write stream from polluting L2.
// ---------------------------------------------------------------------------
__global__ __launch_bounds__(256) void apply_kernel(const float* __restrict__ x,
                                                    float* __restrict__ out) {
    const int pp = (NPLANES / 2 - 1) - blockIdx.x;  // reverse pair index
    const int p0 = 2 * pp;
    const int p1 = 2 * pp + 1;
    const int t  = threadIdx.x;

    const float4 cf0 = __ldcg(&g_coef[p0]);
    const float4 cf1 = __ldcg(&g_coef[p1]);

    const float4* __restrict__ xa = reinterpret_cast<const float4*>(x) + (size_t)p0 * (HW / 4);
    const float4* __restrict__ xb = reinterpret_cast<const float4*>(x) + (size_t)p1 * (HW / 4);
    float4* __restrict__ oa = reinterpret_cast<float4*>(out) + (size_t)p0 * (HW / 4);
    float4* __restrict__ ob = reinterpret_cast<float4*>(out) + (size_t)p1 * (HW / 4);

    // 8 front-batched loads
    float4 a0v = __ldcs(&xa[t]);
    float4 a1v = __ldcs(&xa[t + 256]);
    float4 a2v = __ldcs(&xa[t + 512]);
    float4 a3v = __ldcs(&xa[t + 768]);
    float4 b0v = __ldcs(&xb[t]);
    float4 b1v = __ldcs(&xb[t + 256]);
    float4 b2v = __ldcs(&xb[t + 512]);
    float4 b3v = __ldcs(&xb[t + 768]);

#define APPLY4(r, v, cf)                                                     \
    r.x = fmaxf(fmaf(v.x, cf.x, cf.z), fmaf(v.x, cf.y, cf.w));               \
    r.y = fmaxf(fmaf(v.y, cf.x, cf.z), fmaf(v.y, cf.y, cf.w));               \
    r.z = fmaxf(fmaf(v.z, cf.x, cf.z), fmaf(v.z, cf.y, cf.w));               \
    r.w = fmaxf(fmaf(v.w, cf.x, cf.z), fmaf(v.w, cf.y, cf.w));

    float4 r;
    APPLY4(r, a0v, cf0) __stcs(&oa[t],       r);
    APPLY4(r, a1v, cf0) __stcs(&oa[t + 256], r);
    APPLY4(r, a2v, cf0) __stcs(&oa[t + 512], r);
    APPLY4(r, a3v, cf0) __stcs(&oa[t + 768], r);
    APPLY4(r, b0v, cf1) __stcs(&ob[t],       r);
    APPLY4(r, b1v, cf1) __stcs(&ob[t + 256], r);
    APPLY4(r, b2v, cf1) __stcs(&ob[t + 512], r);
    APPLY4(r, b3v, cf1) __stcs(&ob[t + 768], r);
#undef APPLY4
}

extern "C" void kernel_launch(void* const* d_in, const int* in_sizes, int n_in,
                              void* d_out, int out_size) {
    const float* x  = (const float*)d_in[0];
    const float* w1 = (const float*)d_in[1];
    const float* b1 = (const float*)d_in[2];
    const float* w2 = (const float*)d_in[3];
    const float* b2 = (const float*)d_in[4];
    float* out = (float*)d_out;

    pool_coef_kernel<<<NPLANES, 256>>>(x, w1, b1, w2, b2);
    apply_kernel<<<NPLANES / 2, 256>>>(x, out);
}

// round 5
// speedup vs baseline: 4.5089x; 1.1402x over previous
#include <cuda_runtime.h>
#include <cstdint>

// Fixed shapes from reference setup_inputs
#define BS   32
#define C    256
#define HW   4096          // 64*64
#define HID  32            // C / R
#define NPLANES (BS * C)   // 8192

// Scratch in device globals (no allocations allowed)
__device__ float  g_pooled[NPLANES];   // [BS, C] plane means
__device__ float4 g_coef[NPLANES];     // (a0, a1, q0, q1) per (b,c)

// ---------------------------------------------------------------------------
// Kernel 1: mean pool over H*W. One CTA per plane, 256 threads, 4 float4
// front-batched loads each. No atomics, no fences. Default .ca reads so the
// tail of x stays in L2 for the apply pass.
// ---------------------------------------------------------------------------
__global__ __launch_bounds__(256) void pool_kernel(const float* __restrict__ x) {
    const int p = blockIdx.x;                  // plane = b*C + c
    const int t = threadIdx.x;
    const float4* __restrict__ x4 = reinterpret_cast<const float4*>(x) + (size_t)p * (HW / 4);

    float4 v0 = x4[t];
    float4 v1 = x4[t + 256];
    float4 v2 = x4[t + 512];
    float4 v3 = x4[t + 768];

    float s = ((v0.x + v0.y) + (v0.z + v0.w))
            + ((v1.x + v1.y) + (v1.z + v1.w))
            + ((v2.x + v2.y) + (v2.z + v2.w))
            + ((v3.x + v3.y) + (v3.z + v3.w));

#pragma unroll
    for (int o = 16; o > 0; o >>= 1) s += __shfl_down_sync(0xffffffffu, s, o);

    __shared__ float ws[8];
    if ((t & 31) == 0) ws[t >> 5] = s;
    __syncthreads();
    if (t < 8) {
        float v = ws[t];
#pragma unroll
        for (int o = 4; o > 0; o >>= 1) v += __shfl_down_sync(0xffu, v, o);
        if (t == 0) g_pooled[p] = v * (1.0f / (float)HW);
    }
}

// ---------------------------------------------------------------------------
// Kernel 2: coefficients. One CTA per batch element (32 CTAs, 256 threads).
// Produces per-(b,c) float4 (a0, a1, q0, q1).
// ---------------------------------------------------------------------------
__global__ __launch_bounds__(256) void coef_kernel(const float* __restrict__ w1,
                                                   const float* __restrict__ b1,
                                                   const float* __restrict__ w2,
                                                   const float* __restrict__ b2) {
    const int b = blockIdx.x;
    const int t = threadIdx.x;

    __shared__ float sp[C];    // pooled row
    __shared__ float sh[HID];  // hidden

    sp[t] = g_pooled[b * C + t];
    __syncthreads();

    if (t < HID) {
        float acc = b1[t];
        const float* __restrict__ w1r = w1 + t * C;
#pragma unroll 8
        for (int i = 0; i < C; ++i) acc = fmaf(sp[i], w1r[i], acc);
        sh[t] = fmaxf(acc, 0.f);
    }
    __syncthreads();

    // thread t -> channel t: 4 dot products of length HID
    const int cc = t;
    float z00 = b2[2 * cc];               // k=0 alpha
    float z01 = b2[2 * cc + 1];           // k=0 beta
    float z10 = b2[512 + 2 * cc];         // k=1 alpha
    float z11 = b2[512 + 2 * cc + 1];     // k=1 beta
    const float* __restrict__ r00 = w2 + (size_t)(2 * cc) * HID;
    const float* __restrict__ r01 = w2 + (size_t)(2 * cc + 1) * HID;
    const float* __restrict__ r10 = w2 + (size_t)(512 + 2 * cc) * HID;
    const float* __restrict__ r11 = w2 + (size_t)(512 + 2 * cc + 1) * HID;
#pragma unroll
    for (int h = 0; h < HID; ++h) {
        const float hv = sh[h];
        z00 = fmaf(hv, r00[h], z00);
        z01 = fmaf(hv, r01[h], z01);
        z10 = fmaf(hv, r10[h], z10);
        z11 = fmaf(hv, r11[h], z11);
    }
    float4 cf;
    cf.x = 1.0f + tanhf(0.5f * z00);          // a0 = 1 + 1.0*delta
    cf.y =        tanhf(0.5f * z10);          // a1 = 0 + 1.0*delta
    cf.z = 1.0f + 0.5f * tanhf(0.5f * z01);   // q0 = 1 + 0.5*delta
    cf.w =        0.5f * tanhf(0.5f * z11);   // q1 = 0 + 0.5*delta
    g_coef[b * C + cc] = cf;
}

// ---------------------------------------------------------------------------
// Kernel 3: out = max(x*a0+q0, x*a1+q1). Two planes per CTA, 8 front-batched
// float4 loads per thread (MLP_p1=8). Reverse traversal consumes the tail of
// x left in L2 by the pool pass; __ldcs evicts x after use; __stcs keeps the
// write stream from polluting L2. (Measured 36.4us / 5.8TB/s in R4.)
// ---------------------------------------------------------------------------
__global__ __launch_bounds__(256) void apply_kernel(const float* __restrict__ x,
                                                    float* __restrict__ out) {
    const int pp = (NPLANES / 2 - 1) - blockIdx.x;  // reverse pair index
    const int p0 = 2 * pp;
    const int p1 = 2 * pp + 1;
    const int t  = threadIdx.x;

    const float4 cf0 = __ldcg(&g_coef[p0]);
    const float4 cf1 = __ldcg(&g_coef[p1]);

    const float4* __restrict__ xa = reinterpret_cast<const float4*>(x) + (size_t)p0 * (HW / 4);
    const float4* __restrict__ xb = reinterpret_cast<const float4*>(x) + (size_t)p1 * (HW / 4);
    float4* __restrict__ oa = reinterpret_cast<float4*>(out) + (size_t)p0 * (HW / 4);
    float4* __restrict__ ob = reinterpret_cast<float4*>(out) + (size_t)p1 * (HW / 4);

    // 8 front-batched loads
    float4 a0v = __ldcs(&xa[t]);
    float4 a1v = __ldcs(&xa[t + 256]);
    float4 a2v = __ldcs(&xa[t + 512]);
    float4 a3v = __ldcs(&xa[t + 768]);
    float4 b0v = __ldcs(&xb[t]);
    float4 b1v = __ldcs(&xb[t + 256]);
    float4 b2v = __ldcs(&xb[t + 512]);
    float4 b3v = __ldcs(&xb[t + 768]);

#define APPLY4(r, v, cf)                                                     \
    r.x = fmaxf(fmaf(v.x, cf.x, cf.z), fmaf(v.x, cf.y, cf.w));               \
    r.y = fmaxf(fmaf(v.y, cf.x, cf.z), fmaf(v.y, cf.y, cf.w));               \
    r.z = fmaxf(fmaf(v.z, cf.x, cf.z), fmaf(v.z, cf.y, cf.w));               \
    r.w = fmaxf(fmaf(v.w, cf.x, cf.z), fmaf(v.w, cf.y, cf.w));

    float4 r;
    APPLY4(r, a0v, cf0) __stcs(&oa[t],       r);
    APPLY4(r, a1v, cf0) __stcs(&oa[t + 256], r);
    APPLY4(r, a2v, cf0) __stcs(&oa[t + 512], r);
    APPLY4(r, a3v, cf0) __stcs(&oa[t + 768], r);
    APPLY4(r, b0v, cf1) __stcs(&ob[t],       r);
    APPLY4(r, b1v, cf1) __stcs(&ob[t + 256], r);
    APPLY4(r, b2v, cf1) __stcs(&ob[t + 512], r);
    APPLY4(r, b3v, cf1) __stcs(&ob[t + 768], r);
#undef APPLY4
}

extern "C" void kernel_launch(void* const* d_in, const int* in_sizes, int n_in,
                              void* d_out, int out_size) {
    const float* x  = (const float*)d_in[0];
    const float* w1 = (const float*)d_in[1];
    const float* b1 = (const float*)d_in[2];
    const float* w2 = (const float*)d_in[3];
    const float* b2 = (const float*)d_in[4];
    float* out = (float*)d_out;

    pool_kernel<<<NPLANES, 256>>>(x);
    coef_kernel<<<BS, 256>>>(w1, b1, w2, b2);
    apply_kernel<<<NPLANES / 2, 256>>>(x, out);
}